// round 10
// baseline (speedup 1.0000x reference)
#include <cuda_runtime.h>
#include <stdint.h>

#define NUM_EXPERTS 8
#define BATCH 4096
#define DM 1024
#define VOCAB 32000

#define TM 128                  // rows per chunk
#define BN 320                  // CTA cols: 256 tensor + 64 scalar
#define BNT 256
#define BK 32
#define NKI (DM / BK)           // 32
#define MAXC 40
#define XSROWS (MAXC * TM)      // 5120

// smem byte layout: srow[128] ints | A[2][128][128B] | B[2][320][128B]
#define SM_A 512
#define SM_B (SM_A + 2 * TM * 128)          // 33280
#define SMEM_TOTAL (SM_B + 2 * BN * 128)    // 115200

// ---------------- device scratch ----------------
__device__ int g_rows[BATCH];
__device__ int g_offsets[NUM_EXPERTS + 1];
__device__ int g_chunk_e[MAXC];
__device__ int g_chunk_pm0[MAXC];
__device__ int g_chunk_rows[MAXC];
__device__ int g_nchunks;
__device__ int g_prow[XSROWS];
__device__ float g_xs[(size_t)XSROWS * DM];  // tf32-rounded gathered x

// ---------------------------------------------------------------------------
// Kernel 1: group rows by expert (ptr % 8); ptr dtype auto-detect (R3).
// ---------------------------------------------------------------------------
__global__ void group_rows_kernel(const uint32_t* __restrict__ ptr_words) {
    __shared__ int counts[NUM_EXPERTS];
    __shared__ int cursor[NUM_EXPERTS];
    __shared__ int pad_off[NUM_EXPERTS];
    __shared__ int odd_nonzero;
    const int tid = threadIdx.x;

    if (tid == 0) odd_nonzero = 0;
    if (tid < NUM_EXPERTS) counts[tid] = 0;
    __syncthreads();

    int local_nz = 0;
    for (int i = tid; i < BATCH / 2; i += blockDim.x)
        if (ptr_words[2 * i + 1] != 0u) local_nz = 1;
    if (local_nz) atomicOr(&odd_nonzero, 1);
    __syncthreads();
    const bool is_i64 = (odd_nonzero == 0);

    for (int i = tid; i < BATCH; i += blockDim.x) {
        uint32_t v = is_i64 ? ptr_words[2 * i] : ptr_words[i];
        atomicAdd(&counts[v & (NUM_EXPERTS - 1)], 1);
    }
    __syncthreads();
    if (tid == 0) {
        int acc = 0, nc = 0, pbase = 0;
        for (int e = 0; e < NUM_EXPERTS; e++) {
            g_offsets[e] = acc;
            cursor[e] = acc;
            pad_off[e] = pbase;
            int cnt = counts[e];
            int nch = (cnt + TM - 1) / TM;
            for (int j = 0; j < nch; j++) {
                g_chunk_e[nc] = e;
                g_chunk_pm0[nc] = pbase + j * TM;
                int rem = cnt - j * TM;
                g_chunk_rows[nc] = rem > TM ? TM : rem;
                nc++;
            }
            pbase += nch * TM;
            acc += cnt;
        }
        g_offsets[NUM_EXPERTS] = acc;
        g_nchunks = nc;
    }
    __syncthreads();
    for (int i = tid; i < XSROWS; i += blockDim.x) g_prow[i] = -1;
    for (int i = tid; i < BATCH; i += blockDim.x) {
        uint32_t v = is_i64 ? ptr_words[2 * i] : ptr_words[i];
        int pos = atomicAdd(&cursor[v & (NUM_EXPERTS - 1)], 1);
        g_rows[pos] = i;
    }
    __syncthreads();
    for (int i = tid; i < BATCH; i += blockDim.x) {
        int e = 0;
        while (!(i >= g_offsets[e] && i < g_offsets[e + 1])) e++;
        g_prow[pad_off[e] + (i - g_offsets[e])] = g_rows[i];
    }
}

// ---------------------------------------------------------------------------
// Kernel 2: gather + RN-round x to tf32 (zeros pad).
// ---------------------------------------------------------------------------
__device__ __forceinline__ float to_tf32_rn(float v) {
    uint32_t b;
    asm("cvt.rna.tf32.f32 %0, %1;" : "=r"(b) : "f"(v));
    return __uint_as_float(b);
}
__device__ __forceinline__ uint32_t cvt_tf32_bits(float v) {
    uint32_t b;
    asm("cvt.rna.tf32.f32 %0, %1;" : "=r"(b) : "f"(v));
    return b;
}

__global__ void pack_kernel(const float* __restrict__ x) {
    const int p = blockIdx.x;
    const int r = g_prow[p];
    float4* dst = reinterpret_cast<float4*>(g_xs + (size_t)p * DM);
    if (r >= 0) {
        const float4* src = reinterpret_cast<const float4*>(x + (size_t)r * DM);
        for (int i = threadIdx.x; i < DM / 4; i += blockDim.x) {
            float4 v = src[i];
            v.x = to_tf32_rn(v.x); v.y = to_tf32_rn(v.y);
            v.z = to_tf32_rn(v.z); v.w = to_tf32_rn(v.w);
            dst[i] = v;
        }
    } else {
        float4 z = make_float4(0.f, 0.f, 0.f, 0.f);
        for (int i = threadIdx.x; i < DM / 4; i += blockDim.x) dst[i] = z;
    }
}

// ---------------------------------------------------------------------------
// Kernel 3: warp-specialized hybrid. 384 threads.
// Warps 0-7: tf32 mma.sync on cols [0,256) (64x64 warp tiles, live-skip).
// Warps 8-11: fp32 FFMA on cols [256,320), 8x8 microtile per thread,
// operands from the same cp.async-filled smem stages, lockstep ktiles.
// smem: 16B-unit XOR swizzle u^(row&7) per 128B row.
// ---------------------------------------------------------------------------
__device__ __forceinline__ void mma_tf32(float& d0, float& d1, float& d2, float& d3,
                                         uint32_t a0, uint32_t a1, uint32_t a2, uint32_t a3,
                                         uint32_t b0, uint32_t b1) {
    asm volatile(
        "mma.sync.aligned.m16n8k8.row.col.f32.tf32.tf32.f32 "
        "{%0,%1,%2,%3}, {%4,%5,%6,%7}, {%8,%9}, {%0,%1,%2,%3};"
        : "+f"(d0), "+f"(d1), "+f"(d2), "+f"(d3)
        : "r"(a0), "r"(a1), "r"(a2), "r"(a3), "r"(b0), "r"(b1));
}

__device__ __forceinline__ void cp_async16(uint32_t dst, const void* src) {
    asm volatile("cp.async.cg.shared.global [%0], [%1], 16;" :: "r"(dst), "l"(src));
}
#define CP_COMMIT() asm volatile("cp.async.commit_group;")
#define CP_WAIT(n)  asm volatile("cp.async.wait_group %0;" :: "n"(n))

__global__ void __launch_bounds__(384, 1)
tc_gemm_kernel(const float* __restrict__ W,
               const float* __restrict__ bias,
               float* __restrict__ out) {
    const int cx = blockIdx.x;
    if (cx >= g_nchunks) return;
    const int e = g_chunk_e[cx];
    const int pm0 = g_chunk_pm0[cx];
    const int rows = g_chunk_rows[cx];
    const int n0 = blockIdx.y * BN;

    extern __shared__ char smem[];
    int* srow = reinterpret_cast<int*>(smem);
    uint32_t smb;
    asm("{ .reg .u64 t; cvta.to.shared.u64 t, %1; cvt.u32.u64 %0, t; }"
        : "=r"(smb) : "l"(smem));

    const int tid = threadIdx.x;
    const int w = tid >> 5, lane = tid & 31;
    const bool is_mma = (tid < 256);

    if (tid < TM) srow[tid] = g_prow[pm0 + tid];

    const float* gA0 = g_xs + (size_t)pm0 * DM;
    const float* gB0 = W + ((size_t)e * VOCAB + n0) * DM;

    // ---- cp.async stage fill (MMA threads only; 4 A-units + 10 B-units) ----
    auto issue_stage = [&](int kt, int st) {
        const float* gA = gA0 + kt * BK;
        const float* gB = gB0 + kt * BK;
        const uint32_t dA = smb + SM_A + st * (TM * 128);
        const uint32_t dB = smb + SM_B + st * (BN * 128);
        #pragma unroll
        for (int i = 0; i < 4; i++) {
            int g = tid + 256 * i;
            int m = g >> 3, u = g & 7;
            cp_async16(dA + m * 128 + ((u ^ (m & 7)) << 4), gA + (size_t)m * DM + u * 4);
        }
        #pragma unroll
        for (int i = 0; i < 10; i++) {
            int g = tid + 256 * i;
            int n = g >> 3, u = g & 7;
            cp_async16(dB + n * 128 + ((u ^ (n & 7)) << 4), gB + (size_t)n * DM + u * 4);
        }
    };

    // ---------------- MMA state ----------------
    const int wm = (w & 1) * 64, wn = (w >> 1) * 64;
    const int grp = lane >> 2, c = lane & 3;
    int live = (rows - wm + 15) >> 4;
    if (live < 0) live = 0;
    if (live > 4) live = 4;

    float acc[4][8][4];
    #pragma unroll
    for (int mt = 0; mt < 4; mt++)
        #pragma unroll
        for (int nt = 0; nt < 8; nt++)
            #pragma unroll
            for (int q = 0; q < 4; q++) acc[mt][nt][q] = 0.f;

    // ---------------- scalar state ----------------
    const int st_id = tid - 256;                 // 0..127 for scalar threads
    const int r0 = (st_id & 15) * 8;             // row group
    const int c0 = (st_id >> 4) * 8;             // col group within [256,320)
    float acc_s[8][8];
    #pragma unroll
    for (int i = 0; i < 8; i++)
        #pragma unroll
        for (int j2 = 0; j2 < 8; j2++) acc_s[i][j2] = 0.f;

    if (is_mma) { issue_stage(0, 0); CP_COMMIT(); }

    for (int kt = 0; kt < NKI; kt++) {
        const int st = kt & 1;
        if (is_mma) {
            if (kt + 1 < NKI) { issue_stage(kt + 1, 1 - st); CP_COMMIT(); CP_WAIT(1); }
            else              { CP_WAIT(0); }
        }
        __syncthreads();   // stage kt ready for everyone

        const uint32_t Ab = smb + SM_A + st * (TM * 128);
        const uint32_t Bb = smb + SM_B + st * (BN * 128);

        if (is_mma) {
            if (live > 0) {
                #pragma unroll
                for (int j = 0; j < 4; j++) {
                    const uint32_t u0 = ((uint32_t)(2 * j) ^ grp) << 4;  // unit 2j
                    const uint32_t u1 = u0 ^ 16;                          // unit 2j+1
                    #pragma unroll
                    for (int half = 0; half < 2; half++) {
                        uint32_t bf[4][2];
                        #pragma unroll
                        for (int nt2 = 0; nt2 < 4; nt2++) {
                            int n = wn + (half * 4 + nt2) * 8 + grp;     // n&7 == grp
                            uint32_t base = Bb + n * 128 + (c << 2);
                            bf[nt2][0] = cvt_tf32_bits(*reinterpret_cast<const float*>(smem + (base + u0 - smb)));
                            bf[nt2][1] = cvt_tf32_bits(*reinterpret_cast<const float*>(smem + (base + u1 - smb)));
                        }
                        #pragma unroll
                        for (int mt = 0; mt < 4; mt++) {
                            if (mt >= live) break;
                            int m = wm + mt * 16 + grp;                  // m&7 == grp
                            uint32_t abase = Ab + m * 128 + (c << 2) - smb;
                            uint32_t a0 = *reinterpret_cast<const uint32_t*>(smem + abase + u0);
                            uint32_t a1 = *reinterpret_cast<const uint32_t*>(smem + abase + u0 + 1024);
                            uint32_t a2 = *reinterpret_cast<const uint32_t*>(smem + abase + u1);
                            uint32_t a3 = *reinterpret_cast<const uint32_t*>(smem + abase + u1 + 1024);
                            #pragma unroll
                            for (int nt2 = 0; nt2 < 4; nt2++) {
                                int nt = half * 4 + nt2;
                                mma_tf32(acc[mt][nt][0], acc[mt][nt][1], acc[mt][nt][2], acc[mt][nt][3],
                                         a0, a1, a2, a3, bf[nt2][0], bf[nt2][1]);
                            }
                        }
                    }
                }
            }
        } else if (r0 < rows) {
            // scalar warps: 8x8 microtile, k-quads rotated per row-group
            const int rot = (r0 >> 3) & 7;
            #pragma unroll
            for (int q8 = 0; q8 < 8; q8++) {
                const int u = (q8 + rot) & 7;
                float4 a4[8], b4[8];
                #pragma unroll
                for (int i = 0; i < 8; i++) {
                    int m = r0 + i;                                       // m&7 == i
                    a4[i] = *reinterpret_cast<const float4*>(
                        smem + SM_A + st * (TM * 128) + m * 128 + ((u ^ i) << 4));
                }
                #pragma unroll
                for (int j2 = 0; j2 < 8; j2++) {
                    int n = BNT + c0 + j2;                                // n&7 == j2
                    b4[j2] = *reinterpret_cast<const float4*>(
                        smem + SM_B + st * (BN * 128) + n * 128 + ((u ^ j2) << 4));
                }
                #pragma unroll
                for (int i = 0; i < 8; i++)
                    #pragma unroll
                    for (int j2 = 0; j2 < 8; j2++)
                        acc_s[i][j2] += a4[i].x * b4[j2].x + a4[i].y * b4[j2].y
                                      + a4[i].z * b4[j2].z + a4[i].w * b4[j2].w;
            }
        }
        __syncthreads();   // stage kt fully consumed -> next issue may overwrite
    }

    // ---- epilogue: tensor columns ----
    if (is_mma && live > 0) {
        const float* bp = bias + (size_t)e * VOCAB + n0 + wn + c * 2;
        float2 bias2[8];
        #pragma unroll
        for (int nt = 0; nt < 8; nt++)
            bias2[nt] = *reinterpret_cast<const float2*>(bp + nt * 8);

        #pragma unroll
        for (int mt = 0; mt < 4; mt++) {
            if (mt >= live) break;
            const int rr = wm + mt * 16 + grp;
            const int row0 = srow[rr];
            const int row1 = srow[rr + 8];
            #pragma unroll
            for (int nt = 0; nt < 8; nt++) {
                const int col = n0 + wn + nt * 8 + c * 2;
                if (row0 >= 0) {
                    float2 o = make_float2(acc[mt][nt][0] + bias2[nt].x,
                                           acc[mt][nt][1] + bias2[nt].y);
                    *reinterpret_cast<float2*>(out + (size_t)row0 * VOCAB + col) = o;
                }
                if (row1 >= 0) {
                    float2 o = make_float2(acc[mt][nt][2] + bias2[nt].x,
                                           acc[mt][nt][3] + bias2[nt].y);
                    *reinterpret_cast<float2*>(out + (size_t)row1 * VOCAB + col) = o;
                }
            }
        }
    }

    // ---- epilogue: scalar columns [256,320) ----
    if (!is_mma && r0 < rows) {
        const int colb = n0 + BNT + c0;
        float4 b40 = *reinterpret_cast<const float4*>(bias + (size_t)e * VOCAB + colb);
        float4 b41 = *reinterpret_cast<const float4*>(bias + (size_t)e * VOCAB + colb + 4);
        #pragma unroll
        for (int i = 0; i < 8; i++) {
            const int row = srow[r0 + i];
            if (row >= 0) {
                float4 o0, o1;
                o0.x = acc_s[i][0] + b40.x; o0.y = acc_s[i][1] + b40.y;
                o0.z = acc_s[i][2] + b40.z; o0.w = acc_s[i][3] + b40.w;
                o1.x = acc_s[i][4] + b41.x; o1.y = acc_s[i][5] + b41.y;
                o1.z = acc_s[i][6] + b41.z; o1.w = acc_s[i][7] + b41.w;
                *reinterpret_cast<float4*>(out + (size_t)row * VOCAB + colb) = o0;
                *reinterpret_cast<float4*>(out + (size_t)row * VOCAB + colb + 4) = o1;
            }
        }
    }
}

// ---------------------------------------------------------------------------
// Host launch
// ---------------------------------------------------------------------------
extern "C" void kernel_launch(void* const* d_in, const int* in_sizes, int n_in,
                              void* d_out, int out_size) {
    const float*    x    = (const float*)d_in[0];
    const uint32_t* ptr  = (const uint32_t*)d_in[1];
    const float*    W    = (const float*)d_in[2];
    const float*    bias = (const float*)d_in[3];
    float*          out  = (float*)d_out;

    static bool attr_done = false;
    if (!attr_done) {
        cudaFuncSetAttribute(tc_gemm_kernel,
                             cudaFuncAttributeMaxDynamicSharedMemorySize, SMEM_TOTAL);
        attr_done = true;
    }

    group_rows_kernel<<<1, 1024>>>(ptr);
    pack_kernel<<<XSROWS, 128>>>(x);

    dim3 grid(MAXC, VOCAB / BN);   // chunk-fastest -> L2 absorbs W reuse
    tc_gemm_kernel<<<grid, 384, SMEM_TOTAL>>>(W, bias, out);
}

// round 11
// speedup vs baseline: 2.4771x; 2.4771x over previous
#include <cuda_runtime.h>
#include <stdint.h>

#define NUM_EXPERTS 8
#define BATCH 4096
#define DM 1024
#define VOCAB 32000

#define TM 128                  // rows per chunk = BM
#define BN 256
#define BK 32
#define NKI (DM / BK)           // 32 k-iterations
#define MAXC 40                 // max chunks: 4096/128 + 8 pad
#define XSROWS (MAXC * TM)      // 5120 padded row slots

// ---------------- device scratch (no allocations allowed) ----------------
__device__ int g_rows[BATCH];
__device__ int g_offsets[NUM_EXPERTS + 1];
__device__ int g_chunk_e[MAXC];
__device__ int g_chunk_pm0[MAXC];
__device__ int g_chunk_rows[MAXC];   // valid rows in this chunk (1..128)
__device__ int g_nchunks;
__device__ int g_prow[XSROWS];       // padded slot -> original x row (-1 = pad)

// ---------------------------------------------------------------------------
// Kernel 1: group rows by expert (ptr % 8), build padded 128-row chunk table.
// Pointer dtype auto-detect (JAX x64-off downcasts int64->int32), as in R3.
// ---------------------------------------------------------------------------
__global__ void group_rows_kernel(const uint32_t* __restrict__ ptr_words) {
    __shared__ int counts[NUM_EXPERTS];
    __shared__ int cursor[NUM_EXPERTS];
    __shared__ int pad_off[NUM_EXPERTS];
    __shared__ int odd_nonzero;
    const int tid = threadIdx.x;

    if (tid == 0) odd_nonzero = 0;
    if (tid < NUM_EXPERTS) counts[tid] = 0;
    __syncthreads();

    int local_nz = 0;
    for (int i = tid; i < BATCH / 2; i += blockDim.x)
        if (ptr_words[2 * i + 1] != 0u) local_nz = 1;
    if (local_nz) atomicOr(&odd_nonzero, 1);
    __syncthreads();
    const bool is_i64 = (odd_nonzero == 0);

    for (int i = tid; i < BATCH; i += blockDim.x) {
        uint32_t v = is_i64 ? ptr_words[2 * i] : ptr_words[i];
        atomicAdd(&counts[v & (NUM_EXPERTS - 1)], 1);
    }
    __syncthreads();
    if (tid == 0) {
        int acc = 0, nc = 0, pbase = 0;
        for (int e = 0; e < NUM_EXPERTS; e++) {
            g_offsets[e] = acc;
            cursor[e] = acc;
            pad_off[e] = pbase;
            int cnt = counts[e];
            int nch = (cnt + TM - 1) / TM;
            for (int j = 0; j < nch; j++) {
                g_chunk_e[nc] = e;
                g_chunk_pm0[nc] = pbase + j * TM;
                int rem = cnt - j * TM;
                g_chunk_rows[nc] = rem > TM ? TM : rem;
                nc++;
            }
            pbase += nch * TM;
            acc += cnt;
        }
        g_offsets[NUM_EXPERTS] = acc;
        g_nchunks = nc;
    }
    __syncthreads();
    for (int i = tid; i < XSROWS; i += blockDim.x) g_prow[i] = -1;
    for (int i = tid; i < BATCH; i += blockDim.x) {
        uint32_t v = is_i64 ? ptr_words[2 * i] : ptr_words[i];
        int pos = atomicAdd(&cursor[v & (NUM_EXPERTS - 1)], 1);
        g_rows[pos] = i;
    }
    __syncthreads();
    for (int i = tid; i < BATCH; i += blockDim.x) {
        int e = 0;
        while (!(i >= g_offsets[e] && i < g_offsets[e + 1])) e++;
        g_prow[pad_off[e] + (i - g_offsets[e])] = g_rows[i];
    }
}

// ---------------------------------------------------------------------------
// Kernel 2: tf32 mma.sync GEMM (R8 structure) with FUSED A-gather.
// CTA = 128 rows x 256 vocab cols, 8 warps (2m x 4n), warp tile 64x64,
// BK=32 double-buffered smem with register staging. A rows are gathered
// directly from x via g_prow (tf32 RN rounding applied in-register before
// STS -> bit-identical to the former pack pass). Zero-row MMA elimination
// at 16-row granularity (warp-uniform guard).
// ---------------------------------------------------------------------------
__device__ __forceinline__ float to_tf32_rn(float v) {
    uint32_t b;
    asm("cvt.rna.tf32.f32 %0, %1;" : "=r"(b) : "f"(v));
    return __uint_as_float(b);
}
__device__ __forceinline__ uint32_t cvt_tf32_bits(float v) {
    uint32_t b;
    asm("cvt.rna.tf32.f32 %0, %1;" : "=r"(b) : "f"(v));
    return b;
}

__device__ __forceinline__ void mma_tf32(float& d0, float& d1, float& d2, float& d3,
                                         uint32_t a0, uint32_t a1, uint32_t a2, uint32_t a3,
                                         uint32_t b0, uint32_t b1) {
    asm volatile(
        "mma.sync.aligned.m16n8k8.row.col.f32.tf32.tf32.f32 "
        "{%0,%1,%2,%3}, {%4,%5,%6,%7}, {%8,%9}, {%0,%1,%2,%3};"
        : "+f"(d0), "+f"(d1), "+f"(d2), "+f"(d3)
        : "r"(a0), "r"(a1), "r"(a2), "r"(a3), "r"(b0), "r"(b1));
}

#define SMEM_TOTAL (512 + 2 * 4 * TM * 8 * 4 + 2 * 4 * BN * 8 * 4)  // 98816

__global__ void __launch_bounds__(256, 1)
tc_gemm_kernel(const float* __restrict__ x,
               const float* __restrict__ W,
               const float* __restrict__ bias,
               float* __restrict__ out) {
    const int cx = blockIdx.x;
    if (cx >= g_nchunks) return;
    const int e = g_chunk_e[cx];
    const int pm0 = g_chunk_pm0[cx];
    const int rows = g_chunk_rows[cx];
    const int n0 = blockIdx.y * BN;

    extern __shared__ float sm[];
    int* srow = reinterpret_cast<int*>(sm);         // [128]
    float* As = sm + TM;                            // [2][4][TM][8]
    float* Bs = As + 2 * 4 * TM * 8;                // [2][4][BN][8]

    const int tid = threadIdx.x;
    const int w = tid >> 5, lane = tid & 31;
    const int wm = (w & 1) * 64, wn = (w >> 1) * 64;
    const int grp = lane >> 2, c = lane & 3;

    if (tid < TM) srow[tid] = g_prow[pm0 + tid];

    // live 16-row m-slices for this warp (0..4), warp-uniform
    int live = (rows - wm + 15) >> 4;
    if (live < 0) live = 0;
    if (live > 4) live = 4;

    const float* gW = W + (size_t)e * VOCAB * DM;

    // fused gather: each thread stages two fixed A rows; resolve pointers once
    const int am0 = tid >> 2;                       // rows 0..63
    const int am1 = (tid + 256) >> 2;               // rows 64..127
    const int aj  = (tid & 3);                      // k sub-offset (j*8 floats)
    const int ar0 = g_prow[pm0 + am0];
    const int ar1 = g_prow[pm0 + am1];
    const float* a_src0 = (ar0 >= 0) ? (x + (size_t)ar0 * DM + aj * 8) : nullptr;
    const float* a_src1 = (ar1 >= 0) ? (x + (size_t)ar1 * DM + aj * 8) : nullptr;

    float acc[4][8][4];
    #pragma unroll
    for (int mt = 0; mt < 4; mt++)
        #pragma unroll
        for (int nt = 0; nt < 8; nt++)
            #pragma unroll
            for (int q = 0; q < 4; q++) acc[mt][nt][q] = 0.f;

    float4 pa[2][2];     // A staging: 2 rows x 32B
    float4 pb[4][2];     // B staging: 4 rows x 32B

    auto load_regs = [&](int kt) {
        const int k0 = kt * BK;
        const float4 z = make_float4(0.f, 0.f, 0.f, 0.f);
        if (a_src0) {
            pa[0][0] = *reinterpret_cast<const float4*>(a_src0 + k0);
            pa[0][1] = *reinterpret_cast<const float4*>(a_src0 + k0 + 4);
        } else { pa[0][0] = z; pa[0][1] = z; }
        if (a_src1) {
            pa[1][0] = *reinterpret_cast<const float4*>(a_src1 + k0);
            pa[1][1] = *reinterpret_cast<const float4*>(a_src1 + k0 + 4);
        } else { pa[1][0] = z; pa[1][1] = z; }
        #pragma unroll
        for (int i = 0; i < 4; i++) {
            int u = tid + 256 * i;
            int n = u >> 2, j = u & 3;
            const float* gb = gW + (size_t)(n0 + n) * DM + k0 + j * 8;
            pb[i][0] = *reinterpret_cast<const float4*>(gb);
            pb[i][1] = *reinterpret_cast<const float4*>(gb + 4);
        }
    };

    auto sts = [&](int st) {
        #pragma unroll
        for (int i = 0; i < 2; i++) {
            int m = (i == 0) ? am0 : am1;
            float* base = As + (((st * 4 + aj) * TM + m) << 3);
            float f0[4] = {to_tf32_rn(pa[i][0].x), to_tf32_rn(pa[i][0].y),
                           to_tf32_rn(pa[i][0].z), to_tf32_rn(pa[i][0].w)};
            float f1[4] = {to_tf32_rn(pa[i][1].x), to_tf32_rn(pa[i][1].y),
                           to_tf32_rn(pa[i][1].z), to_tf32_rn(pa[i][1].w)};
            #pragma unroll
            for (int cc = 0; cc < 4; cc++)
                *reinterpret_cast<float2*>(base + ((cc ^ aj) << 1)) = make_float2(f0[cc], f1[cc]);
        }
        #pragma unroll
        for (int i = 0; i < 4; i++) {
            int u = tid + 256 * i;
            int n = u >> 2, j = u & 3;
            float* base = Bs + (((st * 4 + j) * BN + n) << 3);
            float f0[4] = {pb[i][0].x, pb[i][0].y, pb[i][0].z, pb[i][0].w};
            float f1[4] = {pb[i][1].x, pb[i][1].y, pb[i][1].z, pb[i][1].w};
            #pragma unroll
            for (int cc = 0; cc < 4; cc++)
                *reinterpret_cast<float2*>(base + ((cc ^ j) << 1)) = make_float2(f0[cc], f1[cc]);
        }
    };

    auto compute = [&](int st) {
        if (live == 0) return;                 // warp-uniform: whole warp idle
        #pragma unroll
        for (int j = 0; j < 4; j++) {
            const int slot2 = ((c ^ j) << 1);
            const float* Aj = As + ((st * 4 + j) * TM << 3);
            const float* Bj = Bs + ((st * 4 + j) * BN << 3);
            uint32_t bf[8][2];
            #pragma unroll
            for (int nt = 0; nt < 8; nt++) {
                int n = wn + nt * 8 + grp;
                float2 bv = *reinterpret_cast<const float2*>(Bj + (n << 3) + slot2);
                bf[nt][0] = cvt_tf32_bits(bv.x);
                bf[nt][1] = cvt_tf32_bits(bv.y);
            }
            #pragma unroll
            for (int mt = 0; mt < 4; mt++) {
                if (mt >= live) break;         // warp-uniform guard: skip dead slices
                int r0 = wm + mt * 16 + grp;
                float2 a0v = *reinterpret_cast<const float2*>(Aj + (r0 << 3) + slot2);
                float2 a1v = *reinterpret_cast<const float2*>(Aj + ((r0 + 8) << 3) + slot2);
                uint32_t a0 = __float_as_uint(a0v.x);
                uint32_t a1 = __float_as_uint(a1v.x);
                uint32_t a2 = __float_as_uint(a0v.y);
                uint32_t a3 = __float_as_uint(a1v.y);
                #pragma unroll
                for (int nt = 0; nt < 8; nt++)
                    mma_tf32(acc[mt][nt][0], acc[mt][nt][1], acc[mt][nt][2], acc[mt][nt][3],
                             a0, a1, a2, a3, bf[nt][0], bf[nt][1]);
            }
        }
    };

    load_regs(0);
    sts(0);
    __syncthreads();

    for (int kt = 0; kt < NKI; kt++) {
        const int st = kt & 1;
        if (kt + 1 < NKI) load_regs(kt + 1);
        compute(st);
        if (kt + 1 < NKI) {
            sts(1 - st);
            __syncthreads();
        }
    }

    // ---- epilogue: bias + scatter float2 stores ----
    if (live > 0) {
        const float* bp = bias + (size_t)e * VOCAB + n0 + wn + c * 2;
        float2 bias2[8];
        #pragma unroll
        for (int nt = 0; nt < 8; nt++)
            bias2[nt] = *reinterpret_cast<const float2*>(bp + nt * 8);

        #pragma unroll
        for (int mt = 0; mt < 4; mt++) {
            if (mt >= live) break;
            const int r0 = wm + mt * 16 + grp;
            const int row0 = srow[r0];
            const int row1 = srow[r0 + 8];
            #pragma unroll
            for (int nt = 0; nt < 8; nt++) {
                const int col = n0 + wn + nt * 8 + c * 2;
                if (row0 >= 0) {
                    float2 o = make_float2(acc[mt][nt][0] + bias2[nt].x,
                                           acc[mt][nt][1] + bias2[nt].y);
                    *reinterpret_cast<float2*>(out + (size_t)row0 * VOCAB + col) = o;
                }
                if (row1 >= 0) {
                    float2 o = make_float2(acc[mt][nt][2] + bias2[nt].x,
                                           acc[mt][nt][3] + bias2[nt].y);
                    *reinterpret_cast<float2*>(out + (size_t)row1 * VOCAB + col) = o;
                }
            }
        }
    }
}

// ---------------------------------------------------------------------------
// Host launch
// ---------------------------------------------------------------------------
extern "C" void kernel_launch(void* const* d_in, const int* in_sizes, int n_in,
                              void* d_out, int out_size) {
    const float*    x    = (const float*)d_in[0];
    const uint32_t* ptr  = (const uint32_t*)d_in[1];
    const float*    W    = (const float*)d_in[2];
    const float*    bias = (const float*)d_in[3];
    float*          out  = (float*)d_out;

    static bool attr_done = false;
    if (!attr_done) {
        cudaFuncSetAttribute(tc_gemm_kernel,
                             cudaFuncAttributeMaxDynamicSharedMemorySize, SMEM_TOTAL);
        attr_done = true;
    }

    group_rows_kernel<<<1, 1024>>>(ptr);

    dim3 grid(MAXC, VOCAB / BN);   // chunk-fastest -> L2 absorbs W reuse
    tc_gemm_kernel<<<grid, 256, SMEM_TOTAL>>>(x, W, bias, out);
}